// round 8
// baseline (speedup 1.0000x reference)
#include <cuda_runtime.h>
#include <math.h>

// Cox partial likelihood, chunk-sorted (v8):
//   64 chunks of 256 sorted by packed (key(T)<<32|idx) via warp-shuffle bitonic
//   (single-barrier double-buffered SMEM for stride>=32, only 6 such substages);
//   e=exp(theta) gathered post-sort; per-chunk suffix sums via shuffle scan.
//   rank: both-sides-sorted SMEM binary searches (4 chunks/CTA-group, ILP=4).
//   loss: sum 16 partials, gather theta/ev via idx, block-reduce, atomicAdd.

#define NN     16384
#define CH     256              // chunk size (sort tile)
#define NCH    64               // NN / CH
#define RB     512              // rank/loss block size
#define TILES  (NN / RB)        // 32 slot-tiles
#define GROUPS 16
#define CPG    (NCH / GROUPS)   // 4 chunks per group

typedef unsigned long long ull;

__device__ unsigned g_u  [NN];                // sorted keys (chunk-major)
__device__ float    g_sfx[NCH * (CH + 1)];    // suffix sums (+0 sentinel)
__device__ int      g_idx[NN];                // original index per sorted slot
__device__ float    g_part[GROUPS * NN];      // per-group partial rss

__device__ __forceinline__ unsigned key_of(float t) {
    unsigned b = __float_as_uint(t);
    return b ^ ((unsigned)((int)b >> 31) | 0x80000000u);
}

__global__ void __launch_bounds__(CH)
sort_kernel(const float* __restrict__ theta, const float* __restrict__ T,
            int n, float* __restrict__ out) {
    const int c    = blockIdx.x;
    const int t    = threadIdx.x;
    const int lane = t & 31;
    const int w    = t >> 5;
    const int j    = c * CH + t;

    ull kv = (j < n) ? (((ull)key_of(T[j]) << 32) | (unsigned)j) : 0ull;

    __shared__ ull   sbuf[2][CH];
    __shared__ float swarp[CH / 32];
    __shared__ float soff [CH / 32];
    int buf = 0;

    // Bitonic sort ascending (36 substages, 6 with SMEM+1 barrier)
    for (int k = 2; k <= CH; k <<= 1) {
        for (int s = k >> 1; s > 0; s >>= 1) {
            const bool keep_min = (((t & s) == 0) == ((t & k) == 0));
            ull pkv;
            if (s >= 32) {
                sbuf[buf][t] = kv;
                __syncthreads();
                pkv = sbuf[buf][t ^ s];
                buf ^= 1;
            } else {
                pkv = __shfl_xor_sync(0xFFFFFFFFu, kv, s);
            }
            const bool take = keep_min ? (pkv < kv) : (pkv > kv);
            if (take) kv = pkv;
        }
    }

    const unsigned u   = (unsigned)(kv >> 32);
    const int      idx = (int)(unsigned)kv;
    const float    e   = (idx < n) ? expf(theta[idx]) : 0.0f;

    // Inclusive suffix sum of e over sorted positions
    float ssum = e;
#pragma unroll
    for (int off = 1; off < 32; off <<= 1) {
        float v = __shfl_down_sync(0xFFFFFFFFu, ssum, off);
        if (lane + off < 32) ssum += v;
    }
    if (lane == 0) swarp[w] = ssum;
    __syncthreads();
    if (t < CH / 32) {                      // 8 warp totals -> exclusive suffix
        float v = swarp[t];
#pragma unroll
        for (int off = 1; off < CH / 32; off <<= 1) {
            float x = __shfl_down_sync(0xFFu, v, off);
            if (t + off < CH / 32) v += x;
        }
        soff[t] = v - swarp[t];
    }
    __syncthreads();

    g_u  [c * CH + t]       = u;
    g_sfx[c * (CH + 1) + t] = ssum + soff[w];
    g_idx[c * CH + t]       = idx;
    if (t == 0) {
        g_sfx[c * (CH + 1) + CH] = 0.0f;
        if (c == 0) out[0] = 0.0f;          // stream-ordered before loss_kernel
    }
}

// grid = TILES * GROUPS = 512 CTAs; CTA (tile, grp) ranks 512 slot keys
// against 4 chunks of 256 staged in SMEM.
__global__ void __launch_bounds__(RB)
rank_kernel() {
    const int tile = blockIdx.x / GROUPS;
    const int grp  = blockIdx.x % GROUPS;
    const int t    = threadIdx.x;

    __shared__ unsigned ck[CPG][CH];
    __shared__ float    cs[CPG][CH + 1];

    const unsigned u = g_u[tile * RB + t];

    for (int i = t; i < CPG * CH; i += RB) {
        int q = i / CH, r = i % CH;
        ck[q][r] = g_u[(grp * CPG + q) * CH + r];
    }
    for (int i = t; i < CPG * (CH + 1); i += RB) {
        int q = i / (CH + 1), r = i % (CH + 1);
        cs[q][r] = g_sfx[(grp * CPG + q) * (CH + 1) + r];
    }
    __syncthreads();

    int lo[CPG];
#pragma unroll
    for (int q = 0; q < CPG; q++) lo[q] = 0;
#pragma unroll
    for (int s = CH / 2; s > 0; s >>= 1) {       // 8 levels, ILP=4
#pragma unroll
        for (int q = 0; q < CPG; q++)
            if (ck[q][lo[q] + s - 1] < u) lo[q] += s;
    }

    float acc = 0.0f;
#pragma unroll
    for (int q = 0; q < CPG; q++) acc += cs[q][lo[q]];

    g_part[grp * NN + tile * RB + t] = acc;
}

__global__ void __launch_bounds__(RB)
loss_kernel(const float* __restrict__ theta, const float* __restrict__ ev,
            int n, float* __restrict__ out) {
    const int s = blockIdx.x * RB + threadIdx.x;

    float term = 0.0f;
    if (s < n) {
        float rss = 0.0f;
#pragma unroll
        for (int g = 0; g < GROUPS; g++) rss += g_part[g * NN + s];
        const int io = g_idx[s];
        term = (theta[io] - logf(rss)) * ev[io];
    }

    for (int off = 16; off > 0; off >>= 1)
        term += __shfl_down_sync(0xFFFFFFFFu, term, off);

    __shared__ float wsum[RB / 32];
    const int lane = threadIdx.x & 31, warp = threadIdx.x >> 5;
    if (lane == 0) wsum[warp] = term;
    __syncthreads();
    if (threadIdx.x == 0) {
        float ssum = 0.0f;
#pragma unroll
        for (int w = 0; w < RB / 32; w++) ssum += wsum[w];
        atomicAdd(out, -ssum / (float)n);
    }
}

extern "C" void kernel_launch(void* const* d_in, const int* in_sizes, int n_in,
                              void* d_out, int out_size) {
    const float* theta = (const float*)d_in[0];
    const float* T     = (const float*)d_in[1];
    const float* ev    = (const float*)d_in[2];
    float*       out   = (float*)d_out;
    const int n = in_sizes[0];

    sort_kernel<<<NCH, CH>>>(theta, T, n, out);
    rank_kernel<<<TILES * GROUPS, RB>>>();
    loss_kernel<<<TILES, RB>>>(theta, ev, n, out);
}